// round 7
// baseline (speedup 1.0000x reference)
#include <cuda_runtime.h>

// CumulantSOAP_CV: per-column mean & variance over X (200000 x 576 fp32),
// then project (cum - mu) @ W -> (1 x 4).  HBM-bound streaming reduction,
// fused into ONE kernel via software grid barriers (grid = exactly one
// resident wave: 296 blocks = 148 SMs x 2 CTAs, guaranteed by
// __launch_bounds__(576, 2)).

#define N_ROWS   200000
#define P        576
#define NBLK     296
#define RPB      ((N_ROWS + NBLK - 1) / NBLK)   // 676 rows per block
#define NPART    (NBLK * 4)                     // 1184 partial rows
#define NRED     16                              // level-2 reducer blocks
#define ROWS_PER_RED (NPART / NRED)              // 74

// Scratch (allocation-free __device__ globals).
__device__ float g_ps [NPART][P];   // partial sums      (2.7 MB, L2-resident)
__device__ float g_pq [NPART][P];   // partial sum-sqs   (2.7 MB)
__device__ float g_ps2[NRED][P];
__device__ float g_pq2[NRED][P];
__device__ int   g_cnt1;            // zero-init; reset by block 0 at kernel end
__device__ int   g_cnt2;

__global__ __launch_bounds__(576, 2)
void fused_kernel(const float* __restrict__ X,
                  const float* __restrict__ mu,
                  const float* __restrict__ W,
                  float* __restrict__ out) {
    const int b  = blockIdx.x;
    const int t  = threadIdx.x;
    const int c4 = t % 144;      // float4 column index (0..143)
    const int rs = t / 144;      // row phase (0..3)

    // ---------------- Phase 1: streaming reduction (identical to R1) -------
    const int r0 = b * RPB;
    int r1 = r0 + RPB;
    if (r1 > N_ROWS) r1 = N_ROWS;

    const float4* __restrict__ Xv = reinterpret_cast<const float4*>(X);

    float4 s = make_float4(0.f, 0.f, 0.f, 0.f);
    float4 q = make_float4(0.f, 0.f, 0.f, 0.f);

    #pragma unroll 4
    for (int r = r0 + rs; r < r1; r += 4) {
        float4 x = Xv[(size_t)r * 144 + c4];
        s.x += x.x; s.y += x.y; s.z += x.z; s.w += x.w;
        q.x += x.x * x.x; q.y += x.y * x.y; q.z += x.z * x.z; q.w += x.w * x.w;
    }

    const int p = b * 4 + rs;
    reinterpret_cast<float4*>(&g_ps[p][0])[c4] = s;
    reinterpret_cast<float4*>(&g_pq[p][0])[c4] = q;

    // ---------------- Grid barrier #1 --------------------------------------
    __threadfence();
    __syncthreads();
    if (t == 0) atomicAdd(&g_cnt1, 1);

    if (b >= NRED) return;            // 280 blocks arrive and exit

    if (t == 0) {
        while (*(volatile int*)&g_cnt1 < NBLK) __nanosleep(64);
        __threadfence();              // acquire: all partials now visible
    }
    __syncthreads();

    // ---------------- Phase 2: fold 74 partial rows per reducer block ------
    // Thread c owns column c; row reads are fully coalesced across the block.
    {
        const int i0 = b * ROWS_PER_RED;
        float ss = 0.f, qq = 0.f;
        #pragma unroll 2
        for (int i = i0; i < i0 + ROWS_PER_RED; i++) {
            ss += g_ps[i][t];
            qq += g_pq[i][t];
        }
        g_ps2[b][t] = ss;
        g_pq2[b][t] = qq;
    }

    // ---------------- Grid barrier #2 --------------------------------------
    __threadfence();
    __syncthreads();
    if (t == 0) atomicAdd(&g_cnt2, 1);

    if (b != 0) return;

    if (t == 0) {
        while (*(volatile int*)&g_cnt2 < NRED) __nanosleep(64);
        __threadfence();
    }
    __syncthreads();

    // ---------------- Phase 3: final fold + cumulants + projection ---------
    // mom1 == 0 analytically (reference's fp32 residual ~1e-7 is negligible
    // at the 1e-3 output tolerance).
    const int c = t;                  // 0..575
    float s2 = 0.f, q2 = 0.f;
    #pragma unroll
    for (int i = 0; i < NRED; i++) {
        s2 += g_ps2[i][c];
        q2 += g_pq2[i][c];
    }

    const float invN = 1.0f / (float)N_ROWS;
    const float m    = s2 * invN;
    const float mom2 = q2 * invN - m * m;

    const int j0 = 3 * c;
    const float d0 = m    - mu[j0 + 0];
    const float d1 = 0.f  - mu[j0 + 1];
    const float d2 = mom2 - mu[j0 + 2];

    float4 acc;
    acc.x = d0 * W[(j0 + 0) * 4 + 0] + d1 * W[(j0 + 1) * 4 + 0] + d2 * W[(j0 + 2) * 4 + 0];
    acc.y = d0 * W[(j0 + 0) * 4 + 1] + d1 * W[(j0 + 1) * 4 + 1] + d2 * W[(j0 + 2) * 4 + 1];
    acc.z = d0 * W[(j0 + 0) * 4 + 2] + d1 * W[(j0 + 1) * 4 + 2] + d2 * W[(j0 + 2) * 4 + 2];
    acc.w = d0 * W[(j0 + 0) * 4 + 3] + d1 * W[(j0 + 1) * 4 + 3] + d2 * W[(j0 + 2) * 4 + 3];

    __shared__ float4 sh3[576];
    sh3[c] = acc;
    __syncthreads();

    if (c < 64) {
        float4 a = sh3[c];
        for (int i = c + 64; i < 576; i += 64) {
            float4 bb = sh3[i];
            a.x += bb.x; a.y += bb.y; a.z += bb.z; a.w += bb.w;
        }
        sh3[c] = a;
    }
    __syncthreads();
    #pragma unroll
    for (int w = 32; w > 0; w >>= 1) {
        if (c < w) {
            float4 a = sh3[c], bb = sh3[c + w];
            a.x += bb.x; a.y += bb.y; a.z += bb.z; a.w += bb.w;
            sh3[c] = a;
        }
        __syncthreads();
    }

    if (c == 0) {
        out[0] = sh3[0].x;
        out[1] = sh3[0].y;
        out[2] = sh3[0].z;
        out[3] = sh3[0].w;
        // Reset barrier counters for the next graph replay. Safe: all other
        // blocks have completed their final counter accesses and exited.
        g_cnt1 = 0;
        g_cnt2 = 0;
    }
}

extern "C" void kernel_launch(void* const* d_in, const int* in_sizes, int n_in,
                              void* d_out, int out_size) {
    (void)in_sizes; (void)n_in; (void)out_size;
    const float* X  = (const float*)d_in[0];   // (200000, 576)
    const float* mu = (const float*)d_in[1];   // (1728,)
    const float* W  = (const float*)d_in[2];   // (1728, 4)
    float* out = (float*)d_out;                // (1, 4)

    fused_kernel<<<NBLK, 576>>>(X, mu, W, out);
}

// round 8
// speedup vs baseline: 1.0081x; 1.0081x over previous
#include <cuda_runtime.h>

// CumulantSOAP_CV: per-column mean & variance over X (200000 x 576 fp32),
// then project (cum - mu) @ W -> (1 x 4).
// Structure: streaming pass1 kept byte-identical to the best-measured (R1)
// version in its OWN kernel (keeps the hot loop at 35 regs / roofline BW);
// entire tail consolidated into one small 16-block kernel with an internal
// grid barrier (16 blocks are trivially one resident wave).

#define N_ROWS   200000
#define P        576
#define NBLK     296
#define RPB      ((N_ROWS + NBLK - 1) / NBLK)   // 676 rows per block
#define NPART    (NBLK * 4)                     // 1184 partial rows
#define NRED     16
#define ROWS_PER_RED (NPART / NRED)             // 74

// Scratch (allocation-free __device__ globals).
__device__ float g_ps [NPART][P];   // partial sums      (2.7 MB, L2-resident)
__device__ float g_pq [NPART][P];   // partial sum-sqs   (2.7 MB)
__device__ float g_ps2[NRED][P];
__device__ float g_pq2[NRED][P];
__device__ int   g_cnt;             // zero-init; reset by block 0 each run

// ---------------------------------------------------------------------------
// Pass 1: streaming reduction over X. blockDim = 576, grid = 296 (2 CTA/SM).
// BYTE-IDENTICAL to the R1 kernel that measured 68.1us @ 6819 GB/s, 35 regs.
//   thread t -> column group c4 = t % 144 (4 columns via float4),
//               row phase   rs = t / 144 (0..3)
// ---------------------------------------------------------------------------
__global__ __launch_bounds__(576) void pass1_kernel(const float* __restrict__ X) {
    const int b  = blockIdx.x;
    const int t  = threadIdx.x;
    const int c4 = t % 144;      // float4 column index (0..143)
    const int rs = t / 144;      // 0..3

    const int r0 = b * RPB;
    int r1 = r0 + RPB;
    if (r1 > N_ROWS) r1 = N_ROWS;

    const float4* __restrict__ Xv = reinterpret_cast<const float4*>(X);

    float4 s = make_float4(0.f, 0.f, 0.f, 0.f);
    float4 q = make_float4(0.f, 0.f, 0.f, 0.f);

    #pragma unroll 4
    for (int r = r0 + rs; r < r1; r += 4) {
        float4 x = Xv[(size_t)r * 144 + c4];
        s.x += x.x; s.y += x.y; s.z += x.z; s.w += x.w;
        q.x += x.x * x.x; q.y += x.y * x.y; q.z += x.z * x.z; q.w += x.w * x.w;
    }

    const int p = b * 4 + rs;
    reinterpret_cast<float4*>(&g_ps[p][0])[c4] = s;
    reinterpret_cast<float4*>(&g_pq[p][0])[c4] = q;
}

// ---------------------------------------------------------------------------
// Tail: ONE kernel, 16 blocks x 576 threads.
//  stage A: block b folds contiguous rows [b*74, (b+1)*74) of the partials,
//           thread = column (fully coalesced 128B warp loads).
//  grid barrier over the 16 blocks (always co-resident).
//  stage B: block 0 folds the 16 second-level rows, computes cumulants,
//           subtracts mu, projects by W (1728 x 4), tree-reduces to out[4].
// mom1 == 0 analytically (reference's fp32 residual ~1e-7 is negligible at
// the 1e-3 output tolerance).
// ---------------------------------------------------------------------------
__global__ __launch_bounds__(576) void tail_kernel(const float* __restrict__ mu,
                                                   const float* __restrict__ W,
                                                   float* __restrict__ out) {
    const int b = blockIdx.x;     // 0..15
    const int t = threadIdx.x;    // 0..575

    // Stage A: coalesced fold of this block's 74 partial rows.
    {
        const int i0 = b * ROWS_PER_RED;
        float ss = 0.f, qq = 0.f;
        #pragma unroll 2
        for (int i = i0; i < i0 + ROWS_PER_RED; i++) {
            ss += g_ps[i][t];
            qq += g_pq[i][t];
        }
        g_ps2[b][t] = ss;
        g_pq2[b][t] = qq;
    }

    // Grid barrier over 16 blocks.
    __threadfence();
    __syncthreads();
    if (t == 0) atomicAdd(&g_cnt, 1);

    if (b != 0) return;

    if (t == 0) {
        while (*(volatile int*)&g_cnt < NRED) __nanosleep(32);
        __threadfence();              // acquire: all g_ps2/g_pq2 visible
    }
    __syncthreads();

    // Stage B: final fold (coalesced) + cumulants + projection.
    float s2 = 0.f, q2 = 0.f;
    #pragma unroll
    for (int i = 0; i < NRED; i++) {
        s2 += g_ps2[i][t];
        q2 += g_pq2[i][t];
    }

    const float invN = 1.0f / (float)N_ROWS;
    const float m    = s2 * invN;
    const float mom2 = q2 * invN - m * m;

    const int j0 = 3 * t;
    const float d0 = m    - mu[j0 + 0];
    const float d1 = 0.f  - mu[j0 + 1];
    const float d2 = mom2 - mu[j0 + 2];

    float4 acc;
    acc.x = d0 * W[(j0 + 0) * 4 + 0] + d1 * W[(j0 + 1) * 4 + 0] + d2 * W[(j0 + 2) * 4 + 0];
    acc.y = d0 * W[(j0 + 0) * 4 + 1] + d1 * W[(j0 + 1) * 4 + 1] + d2 * W[(j0 + 2) * 4 + 1];
    acc.z = d0 * W[(j0 + 0) * 4 + 2] + d1 * W[(j0 + 1) * 4 + 2] + d2 * W[(j0 + 2) * 4 + 2];
    acc.w = d0 * W[(j0 + 0) * 4 + 3] + d1 * W[(j0 + 1) * 4 + 3] + d2 * W[(j0 + 2) * 4 + 3];

    __shared__ float4 sh[576];
    sh[t] = acc;
    __syncthreads();

    if (t < 64) {
        float4 a = sh[t];
        for (int i = t + 64; i < 576; i += 64) {
            float4 bb = sh[i];
            a.x += bb.x; a.y += bb.y; a.z += bb.z; a.w += bb.w;
        }
        sh[t] = a;
    }
    __syncthreads();
    #pragma unroll
    for (int w = 32; w > 0; w >>= 1) {
        if (t < w) {
            float4 a = sh[t], bb = sh[t + w];
            a.x += bb.x; a.y += bb.y; a.z += bb.z; a.w += bb.w;
            sh[t] = a;
        }
        __syncthreads();
    }

    if (t == 0) {
        out[0] = sh[0].x;
        out[1] = sh[0].y;
        out[2] = sh[0].z;
        out[3] = sh[0].w;
        g_cnt = 0;   // reset for next graph replay (all other blocks done)
    }
}

extern "C" void kernel_launch(void* const* d_in, const int* in_sizes, int n_in,
                              void* d_out, int out_size) {
    (void)in_sizes; (void)n_in; (void)out_size;
    const float* X  = (const float*)d_in[0];   // (200000, 576)
    const float* mu = (const float*)d_in[1];   // (1728,)
    const float* W  = (const float*)d_in[2];   // (1728, 4)
    float* out = (float*)d_out;                // (1, 4)

    pass1_kernel<<<NBLK, 576>>>(X);
    tail_kernel<<<NRED, 576>>>(mu, W, out);
}

// round 10
// speedup vs baseline: 1.0545x; 1.0460x over previous
#include <cuda_runtime.h>

// CumulantSOAP_CV: per-column mean & variance over X (200000 x 576 fp32),
// then project (cum - mu) @ W -> (1 x 4).
// pass1: byte-identical to the best-measured R1 streaming kernel.
// tail:  ONE kernel, latency-optimized: 74 blocks (one per SM), each thread
//        issues a handful of INDEPENDENT float4 loads (high MLP), grid
//        barrier, then block 0 finishes with float4 loads + projection.

#define N_ROWS   200000
#define P        576
#define NBLK     296
#define RPB      ((N_ROWS + NBLK - 1) / NBLK)   // 676 rows per block
#define NPART    (NBLK * 4)                     // 1184 partial rows
#define NRED     74                              // stage-A blocks (<=148: one wave)
#define ROWS_PER_RED (NPART / NRED)              // 16

// Scratch (allocation-free __device__ globals).
__device__ float g_ps [NPART][P];   // partial sums      (2.7 MB)
__device__ float g_pq [NPART][P];   // partial sum-sqs   (2.7 MB)
__device__ float g_ps2[NRED][P];
__device__ float g_pq2[NRED][P];
__device__ int   g_cnt;             // zero-init; reset by block 0 each run

// ---------------------------------------------------------------------------
// Pass 1: streaming reduction over X. blockDim = 576, grid = 296 (2 CTA/SM).
// BYTE-IDENTICAL to the R1 kernel (68.1us @ 6819 GB/s, 35 regs).
// ---------------------------------------------------------------------------
__global__ __launch_bounds__(576) void pass1_kernel(const float* __restrict__ X) {
    const int b  = blockIdx.x;
    const int t  = threadIdx.x;
    const int c4 = t % 144;      // float4 column index (0..143)
    const int rs = t / 144;      // 0..3

    const int r0 = b * RPB;
    int r1 = r0 + RPB;
    if (r1 > N_ROWS) r1 = N_ROWS;

    const float4* __restrict__ Xv = reinterpret_cast<const float4*>(X);

    float4 s = make_float4(0.f, 0.f, 0.f, 0.f);
    float4 q = make_float4(0.f, 0.f, 0.f, 0.f);

    #pragma unroll 4
    for (int r = r0 + rs; r < r1; r += 4) {
        float4 x = Xv[(size_t)r * 144 + c4];
        s.x += x.x; s.y += x.y; s.z += x.z; s.w += x.w;
        q.x += x.x * x.x; q.y += x.y * x.y; q.z += x.z * x.z; q.w += x.w * x.w;
    }

    const int p = b * 4 + rs;
    reinterpret_cast<float4*>(&g_ps[p][0])[c4] = s;
    reinterpret_cast<float4*>(&g_pq[p][0])[c4] = q;
}

// ---------------------------------------------------------------------------
// Tail kernel: 74 blocks x 576 threads. Thread layout (c4 = t%144, rs = t/144).
//  Stage A: block b folds rows [b*16, b*16+16): phase rs takes 4 rows, each a
//           float4 load per array -> 8 independent loads in flight per thread.
//           Phase-fold through smem, coalesced float4 store to g_ps2/g_pq2.
//  Grid barrier over 74 co-resident blocks.
//  Stage B: block 0 folds the 74 rows of g_ps2/g_pq2 the same way (phase rs
//           takes rows rs, rs+4, ...), phase-fold, then cumulants +
//           projection + deterministic tree reduction.
// mom1 == 0 analytically (reference's fp32 residual ~1e-7 is negligible at
// the 1e-3 output tolerance).
// ---------------------------------------------------------------------------
__global__ __launch_bounds__(576) void tail_kernel(const float* __restrict__ mu,
                                                   const float* __restrict__ W,
                                                   float* __restrict__ out) {
    const int b  = blockIdx.x;    // 0..73
    const int t  = threadIdx.x;   // 0..575
    const int c4 = t % 144;
    const int rs = t / 144;       // 0..3

    __shared__ float4 park_s[3][144];
    __shared__ float4 park_q[3][144];

    // ---------------- Stage A --------------------------------------------
    {
        const int i0 = b * ROWS_PER_RED + rs * 4;
        float4 s = make_float4(0.f, 0.f, 0.f, 0.f);
        float4 q = make_float4(0.f, 0.f, 0.f, 0.f);
        #pragma unroll
        for (int k = 0; k < 4; k++) {
            float4 a = reinterpret_cast<const float4*>(&g_ps[i0 + k][0])[c4];
            s.x += a.x; s.y += a.y; s.z += a.z; s.w += a.w;
            float4 e = reinterpret_cast<const float4*>(&g_pq[i0 + k][0])[c4];
            q.x += e.x; q.y += e.y; q.z += e.z; q.w += e.w;
        }
        if (rs > 0) { park_s[rs - 1][c4] = s; park_q[rs - 1][c4] = q; }
        __syncthreads();
        if (rs == 0) {
            #pragma unroll
            for (int ph = 0; ph < 3; ph++) {
                float4 a = park_s[ph][c4];
                s.x += a.x; s.y += a.y; s.z += a.z; s.w += a.w;
                float4 e = park_q[ph][c4];
                q.x += e.x; q.y += e.y; q.z += e.z; q.w += e.w;
            }
            reinterpret_cast<float4*>(&g_ps2[b][0])[c4] = s;
            reinterpret_cast<float4*>(&g_pq2[b][0])[c4] = q;
        }
    }

    // ---------------- Grid barrier over 74 blocks -------------------------
    __threadfence();
    __syncthreads();
    if (t == 0) atomicAdd(&g_cnt, 1);

    if (b != 0) return;

    if (t == 0) {
        while (*(volatile int*)&g_cnt < NRED) __nanosleep(32);
        __threadfence();              // acquire: all g_ps2/g_pq2 visible
    }
    __syncthreads();

    // ---------------- Stage B: fold 74 rows (float4, phase-split) ---------
    float4 s = make_float4(0.f, 0.f, 0.f, 0.f);
    float4 q = make_float4(0.f, 0.f, 0.f, 0.f);
    #pragma unroll 4
    for (int i = rs; i < NRED; i += 4) {
        float4 a = reinterpret_cast<const float4*>(&g_ps2[i][0])[c4];
        s.x += a.x; s.y += a.y; s.z += a.z; s.w += a.w;
        float4 e = reinterpret_cast<const float4*>(&g_pq2[i][0])[c4];
        q.x += e.x; q.y += e.y; q.z += e.z; q.w += e.w;
    }
    if (rs > 0) { park_s[rs - 1][c4] = s; park_q[rs - 1][c4] = q; }
    __syncthreads();

    __shared__ float4 tot_s[144];
    __shared__ float4 tot_q[144];
    if (rs == 0) {
        #pragma unroll
        for (int ph = 0; ph < 3; ph++) {
            float4 a = park_s[ph][c4];
            s.x += a.x; s.y += a.y; s.z += a.z; s.w += a.w;
            float4 e = park_q[ph][c4];
            q.x += e.x; q.y += e.y; q.z += e.z; q.w += e.w;
        }
        tot_s[c4] = s;
        tot_q[c4] = q;
    }
    __syncthreads();

    // ---------------- Cumulants + projection (thread t = column t) --------
    const float s2 = reinterpret_cast<const float*>(tot_s)[t];
    const float q2 = reinterpret_cast<const float*>(tot_q)[t];

    const float invN = 1.0f / (float)N_ROWS;
    const float m    = s2 * invN;
    const float mom2 = q2 * invN - m * m;

    const int j0 = 3 * t;
    const float d0 = m    - mu[j0 + 0];
    const float d1 = 0.f  - mu[j0 + 1];
    const float d2 = mom2 - mu[j0 + 2];

    float4 acc;
    acc.x = d0 * W[(j0 + 0) * 4 + 0] + d1 * W[(j0 + 1) * 4 + 0] + d2 * W[(j0 + 2) * 4 + 0];
    acc.y = d0 * W[(j0 + 0) * 4 + 1] + d1 * W[(j0 + 1) * 4 + 1] + d2 * W[(j0 + 2) * 4 + 1];
    acc.z = d0 * W[(j0 + 0) * 4 + 2] + d1 * W[(j0 + 1) * 4 + 2] + d2 * W[(j0 + 2) * 4 + 2];
    acc.w = d0 * W[(j0 + 0) * 4 + 3] + d1 * W[(j0 + 1) * 4 + 3] + d2 * W[(j0 + 2) * 4 + 3];

    __shared__ float4 sh3[576];
    sh3[t] = acc;
    __syncthreads();

    if (t < 64) {
        float4 a = sh3[t];
        for (int i = t + 64; i < 576; i += 64) {
            float4 bb = sh3[i];
            a.x += bb.x; a.y += bb.y; a.z += bb.z; a.w += bb.w;
        }
        sh3[t] = a;
    }
    __syncthreads();
    #pragma unroll
    for (int w = 32; w > 0; w >>= 1) {
        if (t < w) {
            float4 a = sh3[t], bb = sh3[t + w];
            a.x += bb.x; a.y += bb.y; a.z += bb.z; a.w += bb.w;
            sh3[t] = a;
        }
        __syncthreads();
    }

    if (t == 0) {
        out[0] = sh3[0].x;
        out[1] = sh3[0].y;
        out[2] = sh3[0].z;
        out[3] = sh3[0].w;
        g_cnt = 0;   // reset for next graph replay (all other blocks done)
    }
}

extern "C" void kernel_launch(void* const* d_in, const int* in_sizes, int n_in,
                              void* d_out, int out_size) {
    (void)in_sizes; (void)n_in; (void)out_size;
    const float* X  = (const float*)d_in[0];   // (200000, 576)
    const float* mu = (const float*)d_in[1];   // (1728,)
    const float* W  = (const float*)d_in[2];   // (1728, 4)
    float* out = (float*)d_out;                // (1, 4)

    pass1_kernel<<<NBLK, 576>>>(X);
    tail_kernel<<<NRED, 576>>>(mu, W, out);
}

// round 11
// speedup vs baseline: 1.0848x; 1.0287x over previous
#include <cuda_runtime.h>

// CumulantSOAP_CV: per-column mean & variance over X (200000 x 576 fp32),
// then project (cum - mu) @ W -> (1 x 4).
// pass1: R1 streaming kernel with ONE change: __ldcs (evict-first) on X loads
//        so the 460 MB stream does not evict the partial arrays from L2.
// tail:  byte-identical to R10 (74 blocks, float4 high-MLP fold, grid
//        barrier, block-0 finish). With partials L2-resident it should run
//        at L2 latency instead of DRAM latency.

#define N_ROWS   200000
#define P        576
#define NBLK     296
#define RPB      ((N_ROWS + NBLK - 1) / NBLK)   // 676 rows per block
#define NPART    (NBLK * 4)                     // 1184 partial rows
#define NRED     74                              // stage-A blocks (<=148: one wave)
#define ROWS_PER_RED (NPART / NRED)              // 16

// Scratch (allocation-free __device__ globals).
__device__ float g_ps [NPART][P];   // partial sums      (2.7 MB)
__device__ float g_pq [NPART][P];   // partial sum-sqs   (2.7 MB)
__device__ float g_ps2[NRED][P];
__device__ float g_pq2[NRED][P];
__device__ int   g_cnt;             // zero-init; reset by block 0 each run

// ---------------------------------------------------------------------------
// Pass 1: streaming reduction over X. blockDim = 576, grid = 296 (2 CTA/SM).
// Identical to R1 except __ldcs on the X loads (streaming / evict-first).
// ---------------------------------------------------------------------------
__global__ __launch_bounds__(576) void pass1_kernel(const float* __restrict__ X) {
    const int b  = blockIdx.x;
    const int t  = threadIdx.x;
    const int c4 = t % 144;      // float4 column index (0..143)
    const int rs = t / 144;      // 0..3

    const int r0 = b * RPB;
    int r1 = r0 + RPB;
    if (r1 > N_ROWS) r1 = N_ROWS;

    const float4* __restrict__ Xv = reinterpret_cast<const float4*>(X);

    float4 s = make_float4(0.f, 0.f, 0.f, 0.f);
    float4 q = make_float4(0.f, 0.f, 0.f, 0.f);

    #pragma unroll 4
    for (int r = r0 + rs; r < r1; r += 4) {
        float4 x = __ldcs(&Xv[(size_t)r * 144 + c4]);
        s.x += x.x; s.y += x.y; s.z += x.z; s.w += x.w;
        q.x += x.x * x.x; q.y += x.y * x.y; q.z += x.z * x.z; q.w += x.w * x.w;
    }

    const int p = b * 4 + rs;
    reinterpret_cast<float4*>(&g_ps[p][0])[c4] = s;
    reinterpret_cast<float4*>(&g_pq[p][0])[c4] = q;
}

// ---------------------------------------------------------------------------
// Tail kernel: 74 blocks x 576 threads (byte-identical to R10).
//  Stage A: block b folds rows [b*16, b*16+16): phase rs takes 4 rows, each a
//           float4 load per array -> 8 independent loads in flight per thread.
//           Phase-fold through smem, coalesced float4 store to g_ps2/g_pq2.
//  Grid barrier over 74 co-resident blocks.
//  Stage B: block 0 folds the 74 rows of g_ps2/g_pq2 the same way, then
//           cumulants + projection + deterministic tree reduction.
// mom1 == 0 analytically (reference's fp32 residual ~1e-7 is negligible at
// the 1e-3 output tolerance).
// ---------------------------------------------------------------------------
__global__ __launch_bounds__(576) void tail_kernel(const float* __restrict__ mu,
                                                   const float* __restrict__ W,
                                                   float* __restrict__ out) {
    const int b  = blockIdx.x;    // 0..73
    const int t  = threadIdx.x;   // 0..575
    const int c4 = t % 144;
    const int rs = t / 144;       // 0..3

    __shared__ float4 park_s[3][144];
    __shared__ float4 park_q[3][144];

    // ---------------- Stage A --------------------------------------------
    {
        const int i0 = b * ROWS_PER_RED + rs * 4;
        float4 s = make_float4(0.f, 0.f, 0.f, 0.f);
        float4 q = make_float4(0.f, 0.f, 0.f, 0.f);
        #pragma unroll
        for (int k = 0; k < 4; k++) {
            float4 a = reinterpret_cast<const float4*>(&g_ps[i0 + k][0])[c4];
            s.x += a.x; s.y += a.y; s.z += a.z; s.w += a.w;
            float4 e = reinterpret_cast<const float4*>(&g_pq[i0 + k][0])[c4];
            q.x += e.x; q.y += e.y; q.z += e.z; q.w += e.w;
        }
        if (rs > 0) { park_s[rs - 1][c4] = s; park_q[rs - 1][c4] = q; }
        __syncthreads();
        if (rs == 0) {
            #pragma unroll
            for (int ph = 0; ph < 3; ph++) {
                float4 a = park_s[ph][c4];
                s.x += a.x; s.y += a.y; s.z += a.z; s.w += a.w;
                float4 e = park_q[ph][c4];
                q.x += e.x; q.y += e.y; q.z += e.z; q.w += e.w;
            }
            reinterpret_cast<float4*>(&g_ps2[b][0])[c4] = s;
            reinterpret_cast<float4*>(&g_pq2[b][0])[c4] = q;
        }
    }

    // ---------------- Grid barrier over 74 blocks -------------------------
    __threadfence();
    __syncthreads();
    if (t == 0) atomicAdd(&g_cnt, 1);

    if (b != 0) return;

    if (t == 0) {
        while (*(volatile int*)&g_cnt < NRED) __nanosleep(32);
        __threadfence();              // acquire: all g_ps2/g_pq2 visible
    }
    __syncthreads();

    // ---------------- Stage B: fold 74 rows (float4, phase-split) ---------
    float4 s = make_float4(0.f, 0.f, 0.f, 0.f);
    float4 q = make_float4(0.f, 0.f, 0.f, 0.f);
    #pragma unroll 4
    for (int i = rs; i < NRED; i += 4) {
        float4 a = reinterpret_cast<const float4*>(&g_ps2[i][0])[c4];
        s.x += a.x; s.y += a.y; s.z += a.z; s.w += a.w;
        float4 e = reinterpret_cast<const float4*>(&g_pq2[i][0])[c4];
        q.x += e.x; q.y += e.y; q.z += e.z; q.w += e.w;
    }
    if (rs > 0) { park_s[rs - 1][c4] = s; park_q[rs - 1][c4] = q; }
    __syncthreads();

    __shared__ float4 tot_s[144];
    __shared__ float4 tot_q[144];
    if (rs == 0) {
        #pragma unroll
        for (int ph = 0; ph < 3; ph++) {
            float4 a = park_s[ph][c4];
            s.x += a.x; s.y += a.y; s.z += a.z; s.w += a.w;
            float4 e = park_q[ph][c4];
            q.x += e.x; q.y += e.y; q.z += e.z; q.w += e.w;
        }
        tot_s[c4] = s;
        tot_q[c4] = q;
    }
    __syncthreads();

    // ---------------- Cumulants + projection (thread t = column t) --------
    const float s2 = reinterpret_cast<const float*>(tot_s)[t];
    const float q2 = reinterpret_cast<const float*>(tot_q)[t];

    const float invN = 1.0f / (float)N_ROWS;
    const float m    = s2 * invN;
    const float mom2 = q2 * invN - m * m;

    const int j0 = 3 * t;
    const float d0 = m    - mu[j0 + 0];
    const float d1 = 0.f  - mu[j0 + 1];
    const float d2 = mom2 - mu[j0 + 2];

    float4 acc;
    acc.x = d0 * W[(j0 + 0) * 4 + 0] + d1 * W[(j0 + 1) * 4 + 0] + d2 * W[(j0 + 2) * 4 + 0];
    acc.y = d0 * W[(j0 + 0) * 4 + 1] + d1 * W[(j0 + 1) * 4 + 1] + d2 * W[(j0 + 2) * 4 + 1];
    acc.z = d0 * W[(j0 + 0) * 4 + 2] + d1 * W[(j0 + 1) * 4 + 2] + d2 * W[(j0 + 2) * 4 + 2];
    acc.w = d0 * W[(j0 + 0) * 4 + 3] + d1 * W[(j0 + 1) * 4 + 3] + d2 * W[(j0 + 2) * 4 + 3];

    __shared__ float4 sh3[576];
    sh3[t] = acc;
    __syncthreads();

    if (t < 64) {
        float4 a = sh3[t];
        for (int i = t + 64; i < 576; i += 64) {
            float4 bb = sh3[i];
            a.x += bb.x; a.y += bb.y; a.z += bb.z; a.w += bb.w;
        }
        sh3[t] = a;
    }
    __syncthreads();
    #pragma unroll
    for (int w = 32; w > 0; w >>= 1) {
        if (t < w) {
            float4 a = sh3[t], bb = sh3[t + w];
            a.x += bb.x; a.y += bb.y; a.z += bb.z; a.w += bb.w;
            sh3[t] = a;
        }
        __syncthreads();
    }

    if (t == 0) {
        out[0] = sh3[0].x;
        out[1] = sh3[0].y;
        out[2] = sh3[0].z;
        out[3] = sh3[0].w;
        g_cnt = 0;   // reset for next graph replay (all other blocks done)
    }
}

extern "C" void kernel_launch(void* const* d_in, const int* in_sizes, int n_in,
                              void* d_out, int out_size) {
    (void)in_sizes; (void)n_in; (void)out_size;
    const float* X  = (const float*)d_in[0];   // (200000, 576)
    const float* mu = (const float*)d_in[1];   // (1728,)
    const float* W  = (const float*)d_in[2];   // (1728, 4)
    float* out = (float*)d_out;                // (1, 4)

    pass1_kernel<<<NBLK, 576>>>(X);
    tail_kernel<<<NRED, 576>>>(mu, W, out);
}